// round 14
// baseline (speedup 1.0000x reference)
#include <cuda_runtime.h>
#include <cuda_bf16.h>
#include <cstdint>

// ===================== problem constants =====================
#define NN 8192
#define IN_DIM 512
#define LDIM 256
#define EPS_ADD 1e-10f
#define QSCALE 32000.0f
#define QINV   (1.0f / 32000.0f)

// ===================== scratch (static device globals; no cudaMalloc) =====================
__device__ __align__(16) float          g_xhat[(size_t)NN * LDIM];
__device__ __align__(16) __nv_bfloat16  g_Ap[(size_t)NN * 1024];    // x split  [hi,lo]
__device__ __align__(16) __nv_bfloat16  g_Bp[(size_t)LDIM * 1024];  // pw split [hi,hi]
__device__ __align__(16) __nv_bfloat16  g_Z [(size_t)NN * 256];     // z hi (scores operand)
__device__ __align__(16) short          g_dot[(size_t)NN * NN];     // 134 MB, dot*QSCALE
__device__ unsigned                     g_blk_done[64];             // per row-block tile count (target 65)
__device__ unsigned                     g_row_ctr;                  // softmax row pool

// ===================== helpers =====================
__device__ __forceinline__ uint32_t smem_u32(const void* p) {
    uint32_t a;
    asm("{ .reg .u64 t; cvta.to.shared.u64 t, %1; cvt.u32.u64 %0, t; }"
        : "=r"(a) : "l"(p));
    return a;
}

__device__ __forceinline__ void cpa16(uint32_t saddr, const void* gaddr) {
    asm volatile("cp.async.cg.shared.global [%0], [%1], 16;"
                 :: "r"(saddr), "l"(gaddr) : "memory");
}
#define CP_COMMIT() asm volatile("cp.async.commit_group;" ::: "memory")
#define CP_WAIT1()  asm volatile("cp.async.wait_group 1;" ::: "memory")

__device__ __forceinline__ void ldsm_x4(uint32_t* r, uint32_t addr) {
    asm volatile("ldmatrix.sync.aligned.m8n8.x4.shared.b16 {%0,%1,%2,%3}, [%4];"
                 : "=r"(r[0]), "=r"(r[1]), "=r"(r[2]), "=r"(r[3]) : "r"(addr));
}

__device__ __forceinline__ void mma16816(float* d, const uint32_t* a, const uint32_t* b) {
    asm volatile(
        "mma.sync.aligned.m16n8k16.row.col.f32.bf16.bf16.f32 "
        "{%0,%1,%2,%3}, {%4,%5,%6,%7}, {%8,%9}, {%0,%1,%2,%3};"
        : "+f"(d[0]), "+f"(d[1]), "+f"(d[2]), "+f"(d[3])
        : "r"(a[0]), "r"(a[1]), "r"(a[2]), "r"(a[3]), "r"(b[0]), "r"(b[1]));
}

__device__ __forceinline__ void bsplit(float v, __nv_bfloat16& h, __nv_bfloat16& l) {
    h = __float2bfloat16(v);
    l = __float2bfloat16(v - __bfloat162float(h));
}

// ===================== small kernels =====================
__global__ void k_reset() {
    if (threadIdx.x < 64) g_blk_done[threadIdx.x] = 0u;
    if (threadIdx.x == 64) g_row_ctr = 0u;
}

__global__ __launch_bounds__(256) void k_prep(const float* __restrict__ x,
                                              const float* __restrict__ pw) {
    int idx = blockIdx.x * 256 + threadIdx.x;
    if (idx < NN * IN_DIM) {
        int r = idx >> 9, c = idx & 511;
        __nv_bfloat16 h, l;
        bsplit(x[idx], h, l);
        size_t base = (size_t)r * 1024 + c;
        g_Ap[base]       = h;
        g_Ap[base + 512] = l;
    }
    if (idx < LDIM * IN_DIM) {
        int r = idx >> 9, c = idx & 511;
        __nv_bfloat16 h = __float2bfloat16(pw[idx]);
        size_t base = (size_t)r * 1024 + c;
        g_Bp[base]       = h;
        g_Bp[base + 512] = h;
    }
}

// z = xn * sqrt(w) -> bf16 (hi only). warp-per-row, shuffle reduction.
__global__ __launch_bounds__(256) void k_normalize(const float* __restrict__ lw) {
    const int lane = threadIdx.x & 31;
    const int row  = blockIdx.x * 8 + (threadIdx.x >> 5);
    const float* __restrict__ xr = g_xhat + (size_t)row * LDIM;

    float v[8];
    float s = 0.0f;
    #pragma unroll
    for (int j = 0; j < 8; j++) {
        v[j] = xr[j * 32 + lane];
        s += v[j] * v[j];
    }
    #pragma unroll
    for (int o = 16; o > 0; o >>= 1) s += __shfl_xor_sync(0xffffffffu, s, o);
    float rinv = rsqrtf(s);
    rinv = rinv * (1.5f - 0.5f * s * rinv * rinv);  // Newton -> ~fp32 exact

    size_t base = (size_t)row * 256;
    #pragma unroll
    for (int j = 0; j < 8; j++) {
        int c = j * 32 + lane;
        g_Z[base + c] = __float2bfloat16(v[j] * rinv * sqrtf(lw[c]));
    }
}

// ===================== projection GEMM (float C), 2-stage =====================
template <int KTOT>
__global__ __launch_bounds__(256, 2) void k_gemm(const __nv_bfloat16* __restrict__ A,
                                                 const __nv_bfloat16* __restrict__ B,
                                                 float* __restrict__ C, int ldc) {
    constexpr int KC = 32;
    constexpr int NCH = KTOT / KC;
    __shared__ __align__(16) uint8_t sA[2][128 * 64];
    __shared__ __align__(16) uint8_t sB[2][128 * 64];

    const int tid  = threadIdx.x;
    const int lane = tid & 31;
    const int wid  = tid >> 5;
    const int wm   = wid >> 2;
    const int wn   = wid & 3;
    const int m0   = blockIdx.x * 128;
    const int n0   = blockIdx.y * 128;

    const uint32_t sAu[2] = { smem_u32(sA[0]), smem_u32(sA[1]) };
    const uint32_t sBu[2] = { smem_u32(sB[0]), smem_u32(sB[1]) };

    uint32_t a_base[4]; int a_sw[4];
    #pragma unroll
    for (int mt = 0; mt < 4; mt++) {
        int r = wm * 64 + mt * 16 + (lane & 15);
        a_base[mt] = (uint32_t)(r * 64);
        a_sw[mt]   = (r >> 1) & 3;
    }
    const int a_sel = lane >> 4;
    uint32_t b_base[2]; int b_sw[2];
    #pragma unroll
    for (int p = 0; p < 2; p++) {
        int r = wn * 32 + p * 16 + ((lane >> 4) & 1) * 8 + (lane & 7);
        b_base[p] = (uint32_t)(r * 64);
        b_sw[p]   = (r >> 1) & 3;
    }
    const int b_sel = (lane >> 3) & 1;

    float acc[4][4][4];
    #pragma unroll
    for (int i = 0; i < 4; i++)
        #pragma unroll
        for (int j = 0; j < 4; j++)
            #pragma unroll
            for (int k = 0; k < 4; k++) acc[i][j][k] = 0.0f;

    auto load_chunk = [&](int kc, int st) {
        #pragma unroll
        for (int i = tid; i < 512; i += 256) {
            int row = i >> 2, g = i & 3;
            uint32_t so = (uint32_t)(row * 64 + ((g ^ ((row >> 1) & 3)) << 4));
            cpa16(sAu[st] + so, A + (size_t)(m0 + row) * KTOT + kc * KC + g * 8);
            cpa16(sBu[st] + so, B + (size_t)(n0 + row) * KTOT + kc * KC + g * 8);
        }
    };

    load_chunk(0, 0);
    CP_COMMIT();

    for (int kc = 0; kc < NCH; kc++) {
        const int st = kc & 1;
        if (kc + 1 < NCH) load_chunk(kc + 1, st ^ 1);
        CP_COMMIT();
        CP_WAIT1();
        __syncthreads();

        #pragma unroll
        for (int ks = 0; ks < 2; ks++) {
            uint32_t aF[4][4], bF[4][2];
            #pragma unroll
            for (int mt = 0; mt < 4; mt++) {
                uint32_t addr = sAu[st] + a_base[mt] +
                                (uint32_t)(((2 * ks + a_sel) ^ a_sw[mt]) << 4);
                ldsm_x4(aF[mt], addr);
            }
            #pragma unroll
            for (int p = 0; p < 2; p++) {
                uint32_t r[4];
                uint32_t addr = sBu[st] + b_base[p] +
                                (uint32_t)(((2 * ks + b_sel) ^ b_sw[p]) << 4);
                ldsm_x4(r, addr);
                bF[2 * p][0] = r[0]; bF[2 * p][1] = r[1];
                bF[2 * p + 1][0] = r[2]; bF[2 * p + 1][1] = r[3];
            }
            #pragma unroll
            for (int mt = 0; mt < 4; mt++)
                #pragma unroll
                for (int nt = 0; nt < 4; nt++)
                    mma16816(acc[mt][nt], aF[mt], bF[nt]);
        }
        __syncthreads();
    }

    #pragma unroll
    for (int mt = 0; mt < 4; mt++) {
        #pragma unroll
        for (int nt = 0; nt < 4; nt++) {
            int r0 = m0 + wm * 64 + mt * 16 + (lane >> 2);
            int c0 = n0 + wn * 32 + nt * 8 + 2 * (lane & 3);
            *reinterpret_cast<float2*>(C + (size_t)r0 * ldc + c0)
                = make_float2(acc[mt][nt][0], acc[mt][nt][1]);
            *reinterpret_cast<float2*>(C + (size_t)(r0 + 8) * ldc + c0)
                = make_float2(acc[mt][nt][2], acc[mt][nt][3]);
        }
    }
}

// ===================== symmetric scores GEMM -> int16 dot (K=256, 3-stage) =====================
// R8 config (128x128, 2 CTAs/SM), bm-major tile order + row-block completion counters.
// Row-block b is complete after 65 increments: tiles bm=b (64-b) + tiles bn=b (b+1).
#define STRIDE_ST 130  // shorts per stage row
__global__ __launch_bounds__(256, 2) void k_gemm_sym() {
    constexpr int KTOT = 256, KC = 32, NCH = KTOT / KC;
    __shared__ __align__(16) uint8_t smem_raw[49152];

    // bm-major decode: off(bm) = bm*(129-bm)/2
    const int idx = blockIdx.x;
    int bm = (int)(64.5f - sqrtf(4160.25f - 2.0f * (float)idx));
    if (bm < 0) bm = 0;
    while (bm * (129 - bm) / 2 > idx) bm--;
    while ((bm + 1) * (129 - (bm + 1)) / 2 <= idx) bm++;
    const int bn = bm + (idx - bm * (129 - bm) / 2);
    const int m0 = bm * 128;
    const int n0 = bn * 128;

    const int tid  = threadIdx.x;
    const int lane = tid & 31;
    const int wid  = tid >> 5;
    const int wm   = wid >> 2;
    const int wn   = wid & 3;

    const uint32_t sbase = smem_u32(smem_raw);
    uint32_t sAu[3], sBu[3];
    #pragma unroll
    for (int s = 0; s < 3; s++) {
        sAu[s] = sbase + s * 16384;
        sBu[s] = sbase + s * 16384 + 8192;
    }

    uint32_t a_base[4]; int a_sw[4];
    #pragma unroll
    for (int mt = 0; mt < 4; mt++) {
        int r = wm * 64 + mt * 16 + (lane & 15);
        a_base[mt] = (uint32_t)(r * 64);
        a_sw[mt]   = (r >> 1) & 3;
    }
    const int a_sel = lane >> 4;
    uint32_t b_base[2]; int b_sw[2];
    #pragma unroll
    for (int p = 0; p < 2; p++) {
        int r = wn * 32 + p * 16 + ((lane >> 4) & 1) * 8 + (lane & 7);
        b_base[p] = (uint32_t)(r * 64);
        b_sw[p]   = (r >> 1) & 3;
    }
    const int b_sel = (lane >> 3) & 1;

    float acc[4][4][4];
    #pragma unroll
    for (int i = 0; i < 4; i++)
        #pragma unroll
        for (int j = 0; j < 4; j++)
            #pragma unroll
            for (int k = 0; k < 4; k++) acc[i][j][k] = 0.0f;

    auto load_chunk = [&](int kc, int st) {
        #pragma unroll
        for (int i = tid; i < 512; i += 256) {
            int row = i >> 2, g = i & 3;
            uint32_t so = (uint32_t)(row * 64 + ((g ^ ((row >> 1) & 3)) << 4));
            cpa16(sAu[st] + so, g_Z + (size_t)(m0 + row) * KTOT + kc * KC + g * 8);
            cpa16(sBu[st] + so, g_Z + (size_t)(n0 + row) * KTOT + kc * KC + g * 8);
        }
    };

    load_chunk(0, 0);
    CP_COMMIT();
    load_chunk(1, 1);
    CP_COMMIT();

    for (int kc = 0; kc < NCH; kc++) {
        const int st = kc % 3;
        CP_WAIT1();
        __syncthreads();
        if (kc + 2 < NCH) load_chunk(kc + 2, (kc + 2) % 3);
        CP_COMMIT();

        #pragma unroll
        for (int ks = 0; ks < 2; ks++) {
            uint32_t aF[4][4], bF[4][2];
            #pragma unroll
            for (int mt = 0; mt < 4; mt++) {
                uint32_t addr = sAu[st] + a_base[mt] +
                                (uint32_t)(((2 * ks + a_sel) ^ a_sw[mt]) << 4);
                ldsm_x4(aF[mt], addr);
            }
            #pragma unroll
            for (int p = 0; p < 2; p++) {
                uint32_t r[4];
                uint32_t addr = sBu[st] + b_base[p] +
                                (uint32_t)(((2 * ks + b_sel) ^ b_sw[p]) << 4);
                ldsm_x4(r, addr);
                bF[2 * p][0] = r[0]; bF[2 * p][1] = r[1];
                bF[2 * p + 1][0] = r[2]; bF[2 * p + 1][1] = r[3];
            }
            #pragma unroll
            for (int mt = 0; mt < 4; mt++)
                #pragma unroll
                for (int nt = 0; nt < 4; nt++)
                    mma16816(acc[mt][nt], aF[mt], bF[nt]);
        }
    }
    __syncthreads();  // protect pipeline buffers before epilogue stage reuse

    // ---- epilogue: quantize to int16 stage, then coalesced direct + mirror writes ----
    short* stage = reinterpret_cast<short*>(smem_raw);
    #pragma unroll
    for (int mt = 0; mt < 4; mt++) {
        #pragma unroll
        for (int nt = 0; nt < 4; nt++) {
            int r = wm * 64 + mt * 16 + (lane >> 2);
            int c = wn * 32 + nt * 8 + 2 * (lane & 3);
            short2 q0 = make_short2((short)__float2int_rn(acc[mt][nt][0] * QSCALE),
                                    (short)__float2int_rn(acc[mt][nt][1] * QSCALE));
            short2 q1 = make_short2((short)__float2int_rn(acc[mt][nt][2] * QSCALE),
                                    (short)__float2int_rn(acc[mt][nt][3] * QSCALE));
            *reinterpret_cast<short2*>(&stage[r * STRIDE_ST + c])       = q0;
            *reinterpret_cast<short2*>(&stage[(r + 8) * STRIDE_ST + c]) = q1;
        }
    }
    __syncthreads();

    // direct: C[m0+r][n0+c]
    #pragma unroll 4
    for (int it = 0; it < 32; it++) {
        int i = it * 256 + tid;
        int r = i >> 6, c2 = i & 63;
        short2 q = *reinterpret_cast<const short2*>(&stage[r * STRIDE_ST + 2 * c2]);
        *reinterpret_cast<short2*>(g_dot + (size_t)(m0 + r) * NN + n0 + 2 * c2) = q;
    }
    // mirror: C[n0+c][m0+r]  (skip on diagonal blocks)
    if (bm != bn) {
        #pragma unroll 4
        for (int it = 0; it < 32; it++) {
            int i = it * 256 + tid;
            int mr = i >> 6, c2 = i & 63;
            short2 q = make_short2(stage[(2 * c2) * STRIDE_ST + mr],
                                   stage[(2 * c2 + 1) * STRIDE_ST + mr]);
            *reinterpret_cast<short2*>(g_dot + (size_t)(n0 + mr) * NN + m0 + 2 * c2) = q;
        }
    }

    // release: publish tile completion
    __threadfence();
    __syncthreads();
    if (tid == 0) {
        atomicAdd(&g_blk_done[bm], 1u);
        atomicAdd(&g_blk_done[bn], 1u);
    }
}

// ===================== persistent row softmax: out = adj*exp(-dot) / sum =====================
__global__ __launch_bounds__(256) void k_softmax_p(const float* __restrict__ adj,
                                                   float* __restrict__ out) {
    __shared__ float shs[8];
    __shared__ float b_sum;
    __shared__ unsigned s_row;
    const int t = threadIdx.x;

    for (;;) {
        if (t == 0) s_row = atomicAdd(&g_row_ctr, 1u);
        __syncthreads();
        unsigned row = s_row;
        if (row >= NN) return;

        // wait for the row-block's tiles (acquire)
        if (t == 0) {
            unsigned blk = row >> 7;
            while (atomicAdd(&g_blk_done[blk], 0u) < 65u) __nanosleep(200);
        }
        __syncthreads();
        __threadfence();

        const short* __restrict__ srow = g_dot + (size_t)row * NN;
        const float* __restrict__ arow = adj + (size_t)row * NN;

        float e[32];
        float sum = 0.0f;
        #pragma unroll
        for (int it = 0; it < 8; it++) {
            int i = it * 256 + t;
            uint2 p = __ldcs(reinterpret_cast<const uint2*>(srow + 4 * i));
            short4 q = *reinterpret_cast<const short4*>(&p);
            float4 a = __ldcs(reinterpret_cast<const float4*>(arow + 4 * i));
            float e0 = a.x * __expf((float)q.x * -QINV);
            float e1 = a.y * __expf((float)q.y * -QINV);
            float e2 = a.z * __expf((float)q.z * -QINV);
            float e3 = a.w * __expf((float)q.w * -QINV);
            e[it * 4 + 0] = e0; e[it * 4 + 1] = e1;
            e[it * 4 + 2] = e2; e[it * 4 + 3] = e3;
            sum += (e0 + e1) + (e2 + e3);
        }
        #pragma unroll
        for (int o = 16; o > 0; o >>= 1) sum += __shfl_xor_sync(0xffffffffu, sum, o);
        if ((t & 31) == 0) shs[t >> 5] = sum;
        __syncthreads();
        if (t == 0) {
            float a = 0.0f;
            #pragma unroll
            for (int i = 0; i < 8; i++) a += shs[i];
            b_sum = a;
        }
        __syncthreads();
        float inv = 1.0f / b_sum;
        #pragma unroll
        for (int it = 0; it < 8; it++) {
            int i = it * 256 + t;
            float4 o4 = make_float4(e[it * 4 + 0] * inv + EPS_ADD,
                                    e[it * 4 + 1] * inv + EPS_ADD,
                                    e[it * 4 + 2] * inv + EPS_ADD,
                                    e[it * 4 + 3] * inv + EPS_ADD);
            __stcs(reinterpret_cast<float4*>(out + (size_t)row * NN + 4 * i), o4);
        }
        __syncthreads();  // protect b_sum / s_row before next claim
    }
}

// ===================== streams/events (created once, before capture) =====================
struct OverlapCtx {
    cudaStream_t s1;
    cudaEvent_t evFork, evJoin;
    OverlapCtx() {
        cudaStreamCreateWithFlags(&s1, cudaStreamNonBlocking);
        cudaEventCreateWithFlags(&evFork, cudaEventDisableTiming);
        cudaEventCreateWithFlags(&evJoin, cudaEventDisableTiming);
    }
};
static OverlapCtx g_ovl;

// ===================== launch =====================
extern "C" void kernel_launch(void* const* d_in, const int* in_sizes, int n_in,
                              void* d_out, int out_size) {
    const float* x   = (const float*)d_in[0];
    const float* adj = (const float*)d_in[1];
    const float* pw  = (const float*)d_in[2];
    const float* lw  = (const float*)d_in[3];
    float* out = (float*)d_out;

    __nv_bfloat16 *Ap, *Bp;
    float *xhat;
    cudaGetSymbolAddress((void**)&Ap, g_Ap);
    cudaGetSymbolAddress((void**)&Bp, g_Bp);
    cudaGetSymbolAddress((void**)&xhat, g_xhat);

    k_prep<<<(NN * IN_DIM + 255) / 256, 256>>>(x, pw);
    k_gemm<1024><<<dim3(NN / 128, LDIM / 128, 1), 256>>>(Ap, Bp, xhat, LDIM);
    k_normalize<<<NN / 8, 256>>>(lw);
    k_reset<<<1, 128>>>();

    // fork: softmax consumers on s1, gated by per-row-block counters
    cudaEventRecord(g_ovl.evFork, 0);
    cudaStreamWaitEvent(g_ovl.s1, g_ovl.evFork, 0);

    k_gemm_sym<<<64 * 65 / 2, 256>>>();                 // producer (bm-major)
    k_softmax_p<<<148, 256, 0, g_ovl.s1>>>(adj, out);   // persistent consumers

    // join
    cudaEventRecord(g_ovl.evJoin, g_ovl.s1);
    cudaStreamWaitEvent(0, g_ovl.evJoin, 0);
}

// round 15
// speedup vs baseline: 1.7303x; 1.7303x over previous
#include <cuda_runtime.h>
#include <cuda_bf16.h>
#include <cstdint>

// ===================== problem constants =====================
#define NN 8192
#define IN_DIM 512
#define LDIM 256
#define EPS_ADD 1e-10f
#define QSCALE 32000.0f
#define QINV   (1.0f / 32000.0f)

// ===================== scratch (static device globals; no cudaMalloc) =====================
__device__ __align__(16) float          g_xhat[(size_t)NN * LDIM];
__device__ __align__(16) __nv_bfloat16  g_Ap[(size_t)NN * 1024];    // x split  [hi,lo]
__device__ __align__(16) __nv_bfloat16  g_Bp[(size_t)LDIM * 1024];  // pw split [hi,hi]
__device__ __align__(16) __nv_bfloat16  g_Z [(size_t)NN * 256];     // z hi (scores operand)
__device__ __align__(16) short          g_dot[(size_t)NN * NN];     // 134 MB, dot*QSCALE

// ===================== helpers =====================
__device__ __forceinline__ uint32_t smem_u32(const void* p) {
    uint32_t a;
    asm("{ .reg .u64 t; cvta.to.shared.u64 t, %1; cvt.u32.u64 %0, t; }"
        : "=r"(a) : "l"(p));
    return a;
}

__device__ __forceinline__ void cpa16(uint32_t saddr, const void* gaddr) {
    asm volatile("cp.async.cg.shared.global [%0], [%1], 16;"
                 :: "r"(saddr), "l"(gaddr) : "memory");
}
#define CP_COMMIT() asm volatile("cp.async.commit_group;" ::: "memory")
#define CP_WAIT1()  asm volatile("cp.async.wait_group 1;" ::: "memory")

__device__ __forceinline__ void ldsm_x4(uint32_t* r, uint32_t addr) {
    asm volatile("ldmatrix.sync.aligned.m8n8.x4.shared.b16 {%0,%1,%2,%3}, [%4];"
                 : "=r"(r[0]), "=r"(r[1]), "=r"(r[2]), "=r"(r[3]) : "r"(addr));
}

__device__ __forceinline__ void mma16816(float* d, const uint32_t* a, const uint32_t* b) {
    asm volatile(
        "mma.sync.aligned.m16n8k16.row.col.f32.bf16.bf16.f32 "
        "{%0,%1,%2,%3}, {%4,%5,%6,%7}, {%8,%9}, {%0,%1,%2,%3};"
        : "+f"(d[0]), "+f"(d[1]), "+f"(d[2]), "+f"(d[3])
        : "r"(a[0]), "r"(a[1]), "r"(a[2]), "r"(a[3]), "r"(b[0]), "r"(b[1]));
}

__device__ __forceinline__ void bsplit(float v, __nv_bfloat16& h, __nv_bfloat16& l) {
    h = __float2bfloat16(v);
    l = __float2bfloat16(v - __bfloat162float(h));
}

// ===================== small kernels =====================
__global__ __launch_bounds__(256) void k_prep(const float* __restrict__ x,
                                              const float* __restrict__ pw) {
    int idx = blockIdx.x * 256 + threadIdx.x;
    if (idx < NN * IN_DIM) {
        int r = idx >> 9, c = idx & 511;
        __nv_bfloat16 h, l;
        bsplit(x[idx], h, l);
        size_t base = (size_t)r * 1024 + c;
        g_Ap[base]       = h;
        g_Ap[base + 512] = l;
    }
    if (idx < LDIM * IN_DIM) {
        int r = idx >> 9, c = idx & 511;
        __nv_bfloat16 h = __float2bfloat16(pw[idx]);
        size_t base = (size_t)r * 1024 + c;
        g_Bp[base]       = h;
        g_Bp[base + 512] = h;
    }
}

// z = xn * sqrt(w) -> bf16 (hi only). warp-per-row, shuffle reduction.
__global__ __launch_bounds__(256) void k_normalize(const float* __restrict__ lw) {
    const int lane = threadIdx.x & 31;
    const int row  = blockIdx.x * 8 + (threadIdx.x >> 5);
    const float* __restrict__ xr = g_xhat + (size_t)row * LDIM;

    float v[8];
    float s = 0.0f;
    #pragma unroll
    for (int j = 0; j < 8; j++) {
        v[j] = xr[j * 32 + lane];
        s += v[j] * v[j];
    }
    #pragma unroll
    for (int o = 16; o > 0; o >>= 1) s += __shfl_xor_sync(0xffffffffu, s, o);
    float rinv = rsqrtf(s);
    rinv = rinv * (1.5f - 0.5f * s * rinv * rinv);  // Newton -> ~fp32 exact

    size_t base = (size_t)row * 256;
    #pragma unroll
    for (int j = 0; j < 8; j++) {
        int c = j * 32 + lane;
        g_Z[base + c] = __float2bfloat16(v[j] * rinv * sqrtf(lw[c]));
    }
}

// ===================== projection GEMM (float C), 2-stage =====================
template <int KTOT>
__global__ __launch_bounds__(256, 2) void k_gemm(const __nv_bfloat16* __restrict__ A,
                                                 const __nv_bfloat16* __restrict__ B,
                                                 float* __restrict__ C, int ldc) {
    constexpr int KC = 32;
    constexpr int NCH = KTOT / KC;
    __shared__ __align__(16) uint8_t sA[2][128 * 64];
    __shared__ __align__(16) uint8_t sB[2][128 * 64];

    const int tid  = threadIdx.x;
    const int lane = tid & 31;
    const int wid  = tid >> 5;
    const int wm   = wid >> 2;
    const int wn   = wid & 3;
    const int m0   = blockIdx.x * 128;
    const int n0   = blockIdx.y * 128;

    const uint32_t sAu[2] = { smem_u32(sA[0]), smem_u32(sA[1]) };
    const uint32_t sBu[2] = { smem_u32(sB[0]), smem_u32(sB[1]) };

    uint32_t a_base[4]; int a_sw[4];
    #pragma unroll
    for (int mt = 0; mt < 4; mt++) {
        int r = wm * 64 + mt * 16 + (lane & 15);
        a_base[mt] = (uint32_t)(r * 64);
        a_sw[mt]   = (r >> 1) & 3;
    }
    const int a_sel = lane >> 4;
    uint32_t b_base[2]; int b_sw[2];
    #pragma unroll
    for (int p = 0; p < 2; p++) {
        int r = wn * 32 + p * 16 + ((lane >> 4) & 1) * 8 + (lane & 7);
        b_base[p] = (uint32_t)(r * 64);
        b_sw[p]   = (r >> 1) & 3;
    }
    const int b_sel = (lane >> 3) & 1;

    float acc[4][4][4];
    #pragma unroll
    for (int i = 0; i < 4; i++)
        #pragma unroll
        for (int j = 0; j < 4; j++)
            #pragma unroll
            for (int k = 0; k < 4; k++) acc[i][j][k] = 0.0f;

    auto load_chunk = [&](int kc, int st) {
        #pragma unroll
        for (int i = tid; i < 512; i += 256) {
            int row = i >> 2, g = i & 3;
            uint32_t so = (uint32_t)(row * 64 + ((g ^ ((row >> 1) & 3)) << 4));
            cpa16(sAu[st] + so, A + (size_t)(m0 + row) * KTOT + kc * KC + g * 8);
            cpa16(sBu[st] + so, B + (size_t)(n0 + row) * KTOT + kc * KC + g * 8);
        }
    };

    load_chunk(0, 0);
    CP_COMMIT();

    for (int kc = 0; kc < NCH; kc++) {
        const int st = kc & 1;
        if (kc + 1 < NCH) load_chunk(kc + 1, st ^ 1);
        CP_COMMIT();
        CP_WAIT1();
        __syncthreads();

        #pragma unroll
        for (int ks = 0; ks < 2; ks++) {
            uint32_t aF[4][4], bF[4][2];
            #pragma unroll
            for (int mt = 0; mt < 4; mt++) {
                uint32_t addr = sAu[st] + a_base[mt] +
                                (uint32_t)(((2 * ks + a_sel) ^ a_sw[mt]) << 4);
                ldsm_x4(aF[mt], addr);
            }
            #pragma unroll
            for (int p = 0; p < 2; p++) {
                uint32_t r[4];
                uint32_t addr = sBu[st] + b_base[p] +
                                (uint32_t)(((2 * ks + b_sel) ^ b_sw[p]) << 4);
                ldsm_x4(r, addr);
                bF[2 * p][0] = r[0]; bF[2 * p][1] = r[1];
                bF[2 * p + 1][0] = r[2]; bF[2 * p + 1][1] = r[3];
            }
            #pragma unroll
            for (int mt = 0; mt < 4; mt++)
                #pragma unroll
                for (int nt = 0; nt < 4; nt++)
                    mma16816(acc[mt][nt], aF[mt], bF[nt]);
        }
        __syncthreads();
    }

    #pragma unroll
    for (int mt = 0; mt < 4; mt++) {
        #pragma unroll
        for (int nt = 0; nt < 4; nt++) {
            int r0 = m0 + wm * 64 + mt * 16 + (lane >> 2);
            int c0 = n0 + wn * 32 + nt * 8 + 2 * (lane & 3);
            *reinterpret_cast<float2*>(C + (size_t)r0 * ldc + c0)
                = make_float2(acc[mt][nt][0], acc[mt][nt][1]);
            *reinterpret_cast<float2*>(C + (size_t)(r0 + 8) * ldc + c0)
                = make_float2(acc[mt][nt][2], acc[mt][nt][3]);
        }
    }
}

// ===================== symmetric scores GEMM -> int16 dot (K=256, 3-stage) =====================
// R8 config: 128x128 tiles, upper-tri bn-major, 3-stage cp.async, 2 CTAs/SM.
#define STRIDE_ST 130  // shorts per stage row
__global__ __launch_bounds__(256, 2) void k_gemm_sym() {
    constexpr int KTOT = 256, KC = 32, NCH = KTOT / KC;
    __shared__ __align__(16) uint8_t smem_raw[49152];

    // triangular decode: idx = bn*(bn+1)/2 + bm, bm <= bn
    const int idx = blockIdx.x;
    int bn = (int)((sqrtf(8.0f * (float)idx + 1.0f) - 1.0f) * 0.5f);
    while ((bn + 1) * (bn + 2) / 2 <= idx) bn++;
    while (bn * (bn + 1) / 2 > idx) bn--;
    const int bm = idx - bn * (bn + 1) / 2;
    const int m0 = bm * 128;
    const int n0 = bn * 128;

    const int tid  = threadIdx.x;
    const int lane = tid & 31;
    const int wid  = tid >> 5;
    const int wm   = wid >> 2;
    const int wn   = wid & 3;

    const uint32_t sbase = smem_u32(smem_raw);
    uint32_t sAu[3], sBu[3];
    #pragma unroll
    for (int s = 0; s < 3; s++) {
        sAu[s] = sbase + s * 16384;
        sBu[s] = sbase + s * 16384 + 8192;
    }

    uint32_t a_base[4]; int a_sw[4];
    #pragma unroll
    for (int mt = 0; mt < 4; mt++) {
        int r = wm * 64 + mt * 16 + (lane & 15);
        a_base[mt] = (uint32_t)(r * 64);
        a_sw[mt]   = (r >> 1) & 3;
    }
    const int a_sel = lane >> 4;
    uint32_t b_base[2]; int b_sw[2];
    #pragma unroll
    for (int p = 0; p < 2; p++) {
        int r = wn * 32 + p * 16 + ((lane >> 4) & 1) * 8 + (lane & 7);
        b_base[p] = (uint32_t)(r * 64);
        b_sw[p]   = (r >> 1) & 3;
    }
    const int b_sel = (lane >> 3) & 1;

    float acc[4][4][4];
    #pragma unroll
    for (int i = 0; i < 4; i++)
        #pragma unroll
        for (int j = 0; j < 4; j++)
            #pragma unroll
            for (int k = 0; k < 4; k++) acc[i][j][k] = 0.0f;

    auto load_chunk = [&](int kc, int st) {
        #pragma unroll
        for (int i = tid; i < 512; i += 256) {
            int row = i >> 2, g = i & 3;
            uint32_t so = (uint32_t)(row * 64 + ((g ^ ((row >> 1) & 3)) << 4));
            cpa16(sAu[st] + so, g_Z + (size_t)(m0 + row) * KTOT + kc * KC + g * 8);
            cpa16(sBu[st] + so, g_Z + (size_t)(n0 + row) * KTOT + kc * KC + g * 8);
        }
    };

    load_chunk(0, 0);
    CP_COMMIT();
    load_chunk(1, 1);
    CP_COMMIT();

    for (int kc = 0; kc < NCH; kc++) {
        const int st = kc % 3;
        CP_WAIT1();
        __syncthreads();
        if (kc + 2 < NCH) load_chunk(kc + 2, (kc + 2) % 3);
        CP_COMMIT();

        #pragma unroll
        for (int ks = 0; ks < 2; ks++) {
            uint32_t aF[4][4], bF[4][2];
            #pragma unroll
            for (int mt = 0; mt < 4; mt++) {
                uint32_t addr = sAu[st] + a_base[mt] +
                                (uint32_t)(((2 * ks + a_sel) ^ a_sw[mt]) << 4);
                ldsm_x4(aF[mt], addr);
            }
            #pragma unroll
            for (int p = 0; p < 2; p++) {
                uint32_t r[4];
                uint32_t addr = sBu[st] + b_base[p] +
                                (uint32_t)(((2 * ks + b_sel) ^ b_sw[p]) << 4);
                ldsm_x4(r, addr);
                bF[2 * p][0] = r[0]; bF[2 * p][1] = r[1];
                bF[2 * p + 1][0] = r[2]; bF[2 * p + 1][1] = r[3];
            }
            #pragma unroll
            for (int mt = 0; mt < 4; mt++)
                #pragma unroll
                for (int nt = 0; nt < 4; nt++)
                    mma16816(acc[mt][nt], aF[mt], bF[nt]);
        }
    }
    __syncthreads();  // protect pipeline buffers before epilogue stage reuse

    // ---- epilogue: quantize to int16 stage, then coalesced direct + mirror writes ----
    short* stage = reinterpret_cast<short*>(smem_raw);
    #pragma unroll
    for (int mt = 0; mt < 4; mt++) {
        #pragma unroll
        for (int nt = 0; nt < 4; nt++) {
            int r = wm * 64 + mt * 16 + (lane >> 2);
            int c = wn * 32 + nt * 8 + 2 * (lane & 3);
            short2 q0 = make_short2((short)__float2int_rn(acc[mt][nt][0] * QSCALE),
                                    (short)__float2int_rn(acc[mt][nt][1] * QSCALE));
            short2 q1 = make_short2((short)__float2int_rn(acc[mt][nt][2] * QSCALE),
                                    (short)__float2int_rn(acc[mt][nt][3] * QSCALE));
            *reinterpret_cast<short2*>(&stage[r * STRIDE_ST + c])       = q0;
            *reinterpret_cast<short2*>(&stage[(r + 8) * STRIDE_ST + c]) = q1;
        }
    }
    __syncthreads();

    // direct: C[m0+r][n0+c]
    #pragma unroll 4
    for (int it = 0; it < 32; it++) {
        int i = it * 256 + tid;
        int r = i >> 6, c2 = i & 63;
        short2 q = *reinterpret_cast<const short2*>(&stage[r * STRIDE_ST + 2 * c2]);
        *reinterpret_cast<short2*>(g_dot + (size_t)(m0 + r) * NN + n0 + 2 * c2) = q;
    }
    // mirror: C[n0+c][m0+r]  (skip on diagonal blocks)
    if (bm != bn) {
        #pragma unroll 4
        for (int it = 0; it < 32; it++) {
            int i = it * 256 + tid;
            int mr = i >> 6, c2 = i & 63;
            short2 q = make_short2(stage[(2 * c2) * STRIDE_ST + mr],
                                   stage[(2 * c2 + 1) * STRIDE_ST + mr]);
            *reinterpret_cast<short2*>(g_dot + (size_t)(n0 + mr) * NN + m0 + 2 * c2) = q;
        }
    }
}

// ===================== fused row softmax: out = adj*exp(-dot) / sum =====================
// Rows processed in REVERSE order: gemm_sym writes high row/column blocks last,
// so the freshest dot data is still L2-resident when the first softmax wave reads it.
__global__ __launch_bounds__(256) void k_softmax(const float* __restrict__ adj,
                                                 float* __restrict__ out) {
    __shared__ float shs[8];
    __shared__ float b_sum;
    size_t row = (size_t)(NN - 1 - blockIdx.x);
    int t = threadIdx.x;
    const short* __restrict__ srow = g_dot + row * NN;
    const float* __restrict__ arow = adj + row * NN;

    float e[32];
    float sum = 0.0f;
    #pragma unroll
    for (int it = 0; it < 8; it++) {
        int i = it * 256 + t;
        uint2 p = __ldcs(reinterpret_cast<const uint2*>(srow + 4 * i));
        short4 q = *reinterpret_cast<const short4*>(&p);
        float4 a = __ldcs(reinterpret_cast<const float4*>(arow + 4 * i));
        float e0 = a.x * __expf((float)q.x * -QINV);
        float e1 = a.y * __expf((float)q.y * -QINV);
        float e2 = a.z * __expf((float)q.z * -QINV);
        float e3 = a.w * __expf((float)q.w * -QINV);
        e[it * 4 + 0] = e0; e[it * 4 + 1] = e1;
        e[it * 4 + 2] = e2; e[it * 4 + 3] = e3;
        sum += (e0 + e1) + (e2 + e3);
    }
    #pragma unroll
    for (int o = 16; o > 0; o >>= 1) sum += __shfl_xor_sync(0xffffffffu, sum, o);
    if ((t & 31) == 0) shs[t >> 5] = sum;
    __syncthreads();
    if (t == 0) {
        float a = 0.0f;
        #pragma unroll
        for (int i = 0; i < 8; i++) a += shs[i];
        b_sum = a;
    }
    __syncthreads();
    float inv = 1.0f / b_sum;
    #pragma unroll
    for (int it = 0; it < 8; it++) {
        int i = it * 256 + t;
        float4 o4 = make_float4(e[it * 4 + 0] * inv + EPS_ADD,
                                e[it * 4 + 1] * inv + EPS_ADD,
                                e[it * 4 + 2] * inv + EPS_ADD,
                                e[it * 4 + 3] * inv + EPS_ADD);
        __stcs(reinterpret_cast<float4*>(out + row * NN + 4 * i), o4);
    }
}

// ===================== launch =====================
extern "C" void kernel_launch(void* const* d_in, const int* in_sizes, int n_in,
                              void* d_out, int out_size) {
    const float* x   = (const float*)d_in[0];
    const float* adj = (const float*)d_in[1];
    const float* pw  = (const float*)d_in[2];
    const float* lw  = (const float*)d_in[3];
    float* out = (float*)d_out;

    __nv_bfloat16 *Ap, *Bp;
    float *xhat;
    cudaGetSymbolAddress((void**)&Ap, g_Ap);
    cudaGetSymbolAddress((void**)&Bp, g_Bp);
    cudaGetSymbolAddress((void**)&xhat, g_xhat);

    k_prep<<<(NN * IN_DIM + 255) / 256, 256>>>(x, pw);
    k_gemm<1024><<<dim3(NN / 128, LDIM / 128, 1), 256>>>(Ap, Bp, xhat, LDIM);
    k_normalize<<<NN / 8, 256>>>(lw);
    k_gemm_sym<<<64 * 65 / 2, 256>>>();            // upper-tri blocks, K=256, 3-stage
    k_softmax<<<NN, 256>>>(adj, out);
}

// round 16
// speedup vs baseline: 1.8722x; 1.0820x over previous
#include <cuda_runtime.h>
#include <cuda_bf16.h>
#include <cstdint>

// ===================== problem constants =====================
#define NN 8192
#define IN_DIM 512
#define LDIM 256
#define EPS_ADD 1e-10f
#define QSCALE 32000.0f
#define QINV   (1.0f / 32000.0f)

// ===================== scratch (static device globals; no cudaMalloc) =====================
__device__ __align__(16) float          g_xhat[(size_t)NN * LDIM];
__device__ __align__(16) __nv_bfloat16  g_Ap[(size_t)NN * 512];     // x  (bf16 hi)
__device__ __align__(16) __nv_bfloat16  g_Bp[(size_t)LDIM * 512];   // pw (bf16 hi)
__device__ __align__(16) __nv_bfloat16  g_Z [(size_t)NN * 256];     // z hi (scores operand)
__device__ __align__(16) short          g_dot[(size_t)NN * NN];     // 134 MB, dot*QSCALE

// ===================== helpers =====================
__device__ __forceinline__ uint32_t smem_u32(const void* p) {
    uint32_t a;
    asm("{ .reg .u64 t; cvta.to.shared.u64 t, %1; cvt.u32.u64 %0, t; }"
        : "=r"(a) : "l"(p));
    return a;
}

__device__ __forceinline__ void cpa16(uint32_t saddr, const void* gaddr) {
    asm volatile("cp.async.cg.shared.global [%0], [%1], 16;"
                 :: "r"(saddr), "l"(gaddr) : "memory");
}
#define CP_COMMIT() asm volatile("cp.async.commit_group;" ::: "memory")
#define CP_WAIT1()  asm volatile("cp.async.wait_group 1;" ::: "memory")

__device__ __forceinline__ void ldsm_x4(uint32_t* r, uint32_t addr) {
    asm volatile("ldmatrix.sync.aligned.m8n8.x4.shared.b16 {%0,%1,%2,%3}, [%4];"
                 : "=r"(r[0]), "=r"(r[1]), "=r"(r[2]), "=r"(r[3]) : "r"(addr));
}

__device__ __forceinline__ void mma16816(float* d, const uint32_t* a, const uint32_t* b) {
    asm volatile(
        "mma.sync.aligned.m16n8k16.row.col.f32.bf16.bf16.f32 "
        "{%0,%1,%2,%3}, {%4,%5,%6,%7}, {%8,%9}, {%0,%1,%2,%3};"
        : "+f"(d[0]), "+f"(d[1]), "+f"(d[2]), "+f"(d[3])
        : "r"(a[0]), "r"(a[1]), "r"(a[2]), "r"(a[3]), "r"(b[0]), "r"(b[1]));
}

// ===================== small kernels =====================
// vectorized fp32 -> bf16 conversion (4 elems/thread), streaming
__global__ __launch_bounds__(256) void k_prep(const float* __restrict__ x,
                                              const float* __restrict__ pw) {
    int i = blockIdx.x * 256 + threadIdx.x;
    if (i < NN * IN_DIM / 4) {
        float4 v = __ldcs(reinterpret_cast<const float4*>(x) + i);
        __nv_bfloat162 h0 = __floats2bfloat162_rn(v.x, v.y);
        __nv_bfloat162 h1 = __floats2bfloat162_rn(v.z, v.w);
        uint2 o;
        o.x = *reinterpret_cast<uint32_t*>(&h0);
        o.y = *reinterpret_cast<uint32_t*>(&h1);
        *(reinterpret_cast<uint2*>(g_Ap) + i) = o;
    }
    if (i < LDIM * IN_DIM / 4) {
        float4 v = __ldcs(reinterpret_cast<const float4*>(pw) + i);
        __nv_bfloat162 h0 = __floats2bfloat162_rn(v.x, v.y);
        __nv_bfloat162 h1 = __floats2bfloat162_rn(v.z, v.w);
        uint2 o;
        o.x = *reinterpret_cast<uint32_t*>(&h0);
        o.y = *reinterpret_cast<uint32_t*>(&h1);
        *(reinterpret_cast<uint2*>(g_Bp) + i) = o;
    }
}

// z = xn * sqrt(w) -> bf16 (hi only). warp-per-row, shuffle reduction.
__global__ __launch_bounds__(256) void k_normalize(const float* __restrict__ lw) {
    const int lane = threadIdx.x & 31;
    const int row  = blockIdx.x * 8 + (threadIdx.x >> 5);
    const float* __restrict__ xr = g_xhat + (size_t)row * LDIM;

    float v[8];
    float s = 0.0f;
    #pragma unroll
    for (int j = 0; j < 8; j++) {
        v[j] = xr[j * 32 + lane];
        s += v[j] * v[j];
    }
    #pragma unroll
    for (int o = 16; o > 0; o >>= 1) s += __shfl_xor_sync(0xffffffffu, s, o);
    float rinv = rsqrtf(s);
    rinv = rinv * (1.5f - 0.5f * s * rinv * rinv);  // Newton -> ~fp32 exact

    size_t base = (size_t)row * 256;
    #pragma unroll
    for (int j = 0; j < 8; j++) {
        int c = j * 32 + lane;
        g_Z[base + c] = __float2bfloat16(v[j] * rinv * sqrtf(lw[c]));
    }
}

// ===================== projection GEMM (float C), 2-stage =====================
template <int KTOT>
__global__ __launch_bounds__(256, 2) void k_gemm(const __nv_bfloat16* __restrict__ A,
                                                 const __nv_bfloat16* __restrict__ B,
                                                 float* __restrict__ C, int ldc) {
    constexpr int KC = 32;
    constexpr int NCH = KTOT / KC;
    __shared__ __align__(16) uint8_t sA[2][128 * 64];
    __shared__ __align__(16) uint8_t sB[2][128 * 64];

    const int tid  = threadIdx.x;
    const int lane = tid & 31;
    const int wid  = tid >> 5;
    const int wm   = wid >> 2;
    const int wn   = wid & 3;
    const int m0   = blockIdx.x * 128;
    const int n0   = blockIdx.y * 128;

    const uint32_t sAu[2] = { smem_u32(sA[0]), smem_u32(sA[1]) };
    const uint32_t sBu[2] = { smem_u32(sB[0]), smem_u32(sB[1]) };

    uint32_t a_base[4]; int a_sw[4];
    #pragma unroll
    for (int mt = 0; mt < 4; mt++) {
        int r = wm * 64 + mt * 16 + (lane & 15);
        a_base[mt] = (uint32_t)(r * 64);
        a_sw[mt]   = (r >> 1) & 3;
    }
    const int a_sel = lane >> 4;
    uint32_t b_base[2]; int b_sw[2];
    #pragma unroll
    for (int p = 0; p < 2; p++) {
        int r = wn * 32 + p * 16 + ((lane >> 4) & 1) * 8 + (lane & 7);
        b_base[p] = (uint32_t)(r * 64);
        b_sw[p]   = (r >> 1) & 3;
    }
    const int b_sel = (lane >> 3) & 1;

    float acc[4][4][4];
    #pragma unroll
    for (int i = 0; i < 4; i++)
        #pragma unroll
        for (int j = 0; j < 4; j++)
            #pragma unroll
            for (int k = 0; k < 4; k++) acc[i][j][k] = 0.0f;

    auto load_chunk = [&](int kc, int st) {
        #pragma unroll
        for (int i = tid; i < 512; i += 256) {
            int row = i >> 2, g = i & 3;
            uint32_t so = (uint32_t)(row * 64 + ((g ^ ((row >> 1) & 3)) << 4));
            cpa16(sAu[st] + so, A + (size_t)(m0 + row) * KTOT + kc * KC + g * 8);
            cpa16(sBu[st] + so, B + (size_t)(n0 + row) * KTOT + kc * KC + g * 8);
        }
    };

    load_chunk(0, 0);
    CP_COMMIT();

    for (int kc = 0; kc < NCH; kc++) {
        const int st = kc & 1;
        if (kc + 1 < NCH) load_chunk(kc + 1, st ^ 1);
        CP_COMMIT();
        CP_WAIT1();
        __syncthreads();

        #pragma unroll
        for (int ks = 0; ks < 2; ks++) {
            uint32_t aF[4][4], bF[4][2];
            #pragma unroll
            for (int mt = 0; mt < 4; mt++) {
                uint32_t addr = sAu[st] + a_base[mt] +
                                (uint32_t)(((2 * ks + a_sel) ^ a_sw[mt]) << 4);
                ldsm_x4(aF[mt], addr);
            }
            #pragma unroll
            for (int p = 0; p < 2; p++) {
                uint32_t r[4];
                uint32_t addr = sBu[st] + b_base[p] +
                                (uint32_t)(((2 * ks + b_sel) ^ b_sw[p]) << 4);
                ldsm_x4(r, addr);
                bF[2 * p][0] = r[0]; bF[2 * p][1] = r[1];
                bF[2 * p + 1][0] = r[2]; bF[2 * p + 1][1] = r[3];
            }
            #pragma unroll
            for (int mt = 0; mt < 4; mt++)
                #pragma unroll
                for (int nt = 0; nt < 4; nt++)
                    mma16816(acc[mt][nt], aF[mt], bF[nt]);
        }
        __syncthreads();
    }

    #pragma unroll
    for (int mt = 0; mt < 4; mt++) {
        #pragma unroll
        for (int nt = 0; nt < 4; nt++) {
            int r0 = m0 + wm * 64 + mt * 16 + (lane >> 2);
            int c0 = n0 + wn * 32 + nt * 8 + 2 * (lane & 3);
            *reinterpret_cast<float2*>(C + (size_t)r0 * ldc + c0)
                = make_float2(acc[mt][nt][0], acc[mt][nt][1]);
            *reinterpret_cast<float2*>(C + (size_t)(r0 + 8) * ldc + c0)
                = make_float2(acc[mt][nt][2], acc[mt][nt][3]);
        }
    }
}

// ===================== symmetric scores GEMM -> int16 dot (K=256, 3-stage) =====================
// R8 config: 128x128 tiles, upper-tri bn-major, 3-stage cp.async, 2 CTAs/SM.
#define STRIDE_ST 130  // shorts per stage row
__global__ __launch_bounds__(256, 2) void k_gemm_sym() {
    constexpr int KTOT = 256, KC = 32, NCH = KTOT / KC;
    __shared__ __align__(16) uint8_t smem_raw[49152];

    // triangular decode: idx = bn*(bn+1)/2 + bm, bm <= bn
    const int idx = blockIdx.x;
    int bn = (int)((sqrtf(8.0f * (float)idx + 1.0f) - 1.0f) * 0.5f);
    while ((bn + 1) * (bn + 2) / 2 <= idx) bn++;
    while (bn * (bn + 1) / 2 > idx) bn--;
    const int bm = idx - bn * (bn + 1) / 2;
    const int m0 = bm * 128;
    const int n0 = bn * 128;

    const int tid  = threadIdx.x;
    const int lane = tid & 31;
    const int wid  = tid >> 5;
    const int wm   = wid >> 2;
    const int wn   = wid & 3;

    const uint32_t sbase = smem_u32(smem_raw);
    uint32_t sAu[3], sBu[3];
    #pragma unroll
    for (int s = 0; s < 3; s++) {
        sAu[s] = sbase + s * 16384;
        sBu[s] = sbase + s * 16384 + 8192;
    }

    uint32_t a_base[4]; int a_sw[4];
    #pragma unroll
    for (int mt = 0; mt < 4; mt++) {
        int r = wm * 64 + mt * 16 + (lane & 15);
        a_base[mt] = (uint32_t)(r * 64);
        a_sw[mt]   = (r >> 1) & 3;
    }
    const int a_sel = lane >> 4;
    uint32_t b_base[2]; int b_sw[2];
    #pragma unroll
    for (int p = 0; p < 2; p++) {
        int r = wn * 32 + p * 16 + ((lane >> 4) & 1) * 8 + (lane & 7);
        b_base[p] = (uint32_t)(r * 64);
        b_sw[p]   = (r >> 1) & 3;
    }
    const int b_sel = (lane >> 3) & 1;

    float acc[4][4][4];
    #pragma unroll
    for (int i = 0; i < 4; i++)
        #pragma unroll
        for (int j = 0; j < 4; j++)
            #pragma unroll
            for (int k = 0; k < 4; k++) acc[i][j][k] = 0.0f;

    auto load_chunk = [&](int kc, int st) {
        #pragma unroll
        for (int i = tid; i < 512; i += 256) {
            int row = i >> 2, g = i & 3;
            uint32_t so = (uint32_t)(row * 64 + ((g ^ ((row >> 1) & 3)) << 4));
            cpa16(sAu[st] + so, g_Z + (size_t)(m0 + row) * KTOT + kc * KC + g * 8);
            cpa16(sBu[st] + so, g_Z + (size_t)(n0 + row) * KTOT + kc * KC + g * 8);
        }
    };

    load_chunk(0, 0);
    CP_COMMIT();
    load_chunk(1, 1);
    CP_COMMIT();

    for (int kc = 0; kc < NCH; kc++) {
        const int st = kc % 3;
        CP_WAIT1();
        __syncthreads();
        if (kc + 2 < NCH) load_chunk(kc + 2, (kc + 2) % 3);
        CP_COMMIT();

        #pragma unroll
        for (int ks = 0; ks < 2; ks++) {
            uint32_t aF[4][4], bF[4][2];
            #pragma unroll
            for (int mt = 0; mt < 4; mt++) {
                uint32_t addr = sAu[st] + a_base[mt] +
                                (uint32_t)(((2 * ks + a_sel) ^ a_sw[mt]) << 4);
                ldsm_x4(aF[mt], addr);
            }
            #pragma unroll
            for (int p = 0; p < 2; p++) {
                uint32_t r[4];
                uint32_t addr = sBu[st] + b_base[p] +
                                (uint32_t)(((2 * ks + b_sel) ^ b_sw[p]) << 4);
                ldsm_x4(r, addr);
                bF[2 * p][0] = r[0]; bF[2 * p][1] = r[1];
                bF[2 * p + 1][0] = r[2]; bF[2 * p + 1][1] = r[3];
            }
            #pragma unroll
            for (int mt = 0; mt < 4; mt++)
                #pragma unroll
                for (int nt = 0; nt < 4; nt++)
                    mma16816(acc[mt][nt], aF[mt], bF[nt]);
        }
    }
    __syncthreads();  // protect pipeline buffers before epilogue stage reuse

    // ---- epilogue: quantize to int16 stage, then coalesced direct + mirror writes ----
    short* stage = reinterpret_cast<short*>(smem_raw);
    #pragma unroll
    for (int mt = 0; mt < 4; mt++) {
        #pragma unroll
        for (int nt = 0; nt < 4; nt++) {
            int r = wm * 64 + mt * 16 + (lane >> 2);
            int c = wn * 32 + nt * 8 + 2 * (lane & 3);
            short2 q0 = make_short2((short)__float2int_rn(acc[mt][nt][0] * QSCALE),
                                    (short)__float2int_rn(acc[mt][nt][1] * QSCALE));
            short2 q1 = make_short2((short)__float2int_rn(acc[mt][nt][2] * QSCALE),
                                    (short)__float2int_rn(acc[mt][nt][3] * QSCALE));
            *reinterpret_cast<short2*>(&stage[r * STRIDE_ST + c])       = q0;
            *reinterpret_cast<short2*>(&stage[(r + 8) * STRIDE_ST + c]) = q1;
        }
    }
    __syncthreads();

    // direct: C[m0+r][n0+c]
    #pragma unroll 4
    for (int it = 0; it < 32; it++) {
        int i = it * 256 + tid;
        int r = i >> 6, c2 = i & 63;
        short2 q = *reinterpret_cast<const short2*>(&stage[r * STRIDE_ST + 2 * c2]);
        *reinterpret_cast<short2*>(g_dot + (size_t)(m0 + r) * NN + n0 + 2 * c2) = q;
    }
    // mirror: C[n0+c][m0+r]  (skip on diagonal blocks)
    if (bm != bn) {
        #pragma unroll 4
        for (int it = 0; it < 32; it++) {
            int i = it * 256 + tid;
            int mr = i >> 6, c2 = i & 63;
            short2 q = make_short2(stage[(2 * c2) * STRIDE_ST + mr],
                                   stage[(2 * c2 + 1) * STRIDE_ST + mr]);
            *reinterpret_cast<short2*>(g_dot + (size_t)(n0 + mr) * NN + m0 + 2 * c2) = q;
        }
    }
}

// ===================== fused row softmax: out = adj*exp(-dot) / sum =====================
// Rows processed in REVERSE order: gemm_sym writes high row/column blocks last,
// so the freshest dot data is still L2-resident when the first softmax wave reads it.
__global__ __launch_bounds__(256) void k_softmax(const float* __restrict__ adj,
                                                 float* __restrict__ out) {
    __shared__ float shs[8];
    __shared__ float b_sum;
    size_t row = (size_t)(NN - 1 - blockIdx.x);
    int t = threadIdx.x;
    const short* __restrict__ srow = g_dot + row * NN;
    const float* __restrict__ arow = adj + row * NN;

    float e[32];
    float sum = 0.0f;
    #pragma unroll
    for (int it = 0; it < 8; it++) {
        int i = it * 256 + t;
        uint2 p = __ldcs(reinterpret_cast<const uint2*>(srow + 4 * i));
        short4 q = *reinterpret_cast<const short4*>(&p);
        float4 a = __ldcs(reinterpret_cast<const float4*>(arow + 4 * i));
        float e0 = a.x * __expf((float)q.x * -QINV);
        float e1 = a.y * __expf((float)q.y * -QINV);
        float e2 = a.z * __expf((float)q.z * -QINV);
        float e3 = a.w * __expf((float)q.w * -QINV);
        e[it * 4 + 0] = e0; e[it * 4 + 1] = e1;
        e[it * 4 + 2] = e2; e[it * 4 + 3] = e3;
        sum += (e0 + e1) + (e2 + e3);
    }
    #pragma unroll
    for (int o = 16; o > 0; o >>= 1) sum += __shfl_xor_sync(0xffffffffu, sum, o);
    if ((t & 31) == 0) shs[t >> 5] = sum;
    __syncthreads();
    if (t == 0) {
        float a = 0.0f;
        #pragma unroll
        for (int i = 0; i < 8; i++) a += shs[i];
        b_sum = a;
    }
    __syncthreads();
    float inv = 1.0f / b_sum;
    #pragma unroll
    for (int it = 0; it < 8; it++) {
        int i = it * 256 + t;
        float4 o4 = make_float4(e[it * 4 + 0] * inv + EPS_ADD,
                                e[it * 4 + 1] * inv + EPS_ADD,
                                e[it * 4 + 2] * inv + EPS_ADD,
                                e[it * 4 + 3] * inv + EPS_ADD);
        __stcs(reinterpret_cast<float4*>(out + row * NN + 4 * i), o4);
    }
}

// ===================== launch =====================
extern "C" void kernel_launch(void* const* d_in, const int* in_sizes, int n_in,
                              void* d_out, int out_size) {
    const float* x   = (const float*)d_in[0];
    const float* adj = (const float*)d_in[1];
    const float* pw  = (const float*)d_in[2];
    const float* lw  = (const float*)d_in[3];
    float* out = (float*)d_out;

    __nv_bfloat16 *Ap, *Bp;
    float *xhat;
    cudaGetSymbolAddress((void**)&Ap, g_Ap);
    cudaGetSymbolAddress((void**)&Bp, g_Bp);
    cudaGetSymbolAddress((void**)&xhat, g_xhat);

    k_prep<<<(NN * IN_DIM / 4 + 255) / 256, 256>>>(x, pw);
    k_gemm<512><<<dim3(NN / 128, LDIM / 128, 1), 256>>>(Ap, Bp, xhat, LDIM);
    k_normalize<<<NN / 8, 256>>>(lw);
    k_gemm_sym<<<64 * 65 / 2, 256>>>();            // upper-tri blocks, K=256, 3-stage
    k_softmax<<<NN, 256>>>(adj, out);
}